// round 5
// baseline (speedup 1.0000x reference)
#include <cuda_runtime.h>
#include <math_constants.h>

#define BS 32
#define NQ 256
#define NT 128
#define NC 2048
#define BT (BS * NT)                  // 4096
#define CSIZE ((size_t)BS * NQ * BT)  // 33554432

// Sortable-integer mapping for IEEE f64 (no NaN / -0.0 appears here):
// unsigned order of keys == numeric order of doubles.
static __device__ __forceinline__ unsigned long long dkey(double x) {
    unsigned long long b = (unsigned long long)__double_as_longlong(x);
    return (b & 0x8000000000000000ULL) ? ~b : (b | 0x8000000000000000ULL);
}
static __device__ __forceinline__ double dunkey(unsigned long long k) {
    unsigned long long b = (k & 0x8000000000000000ULL) ? (k ^ 0x8000000000000000ULL) : ~k;
    return __longlong_as_double((long long)b);
}

// ---------------------------------------------------------------------------
// Kernel 1: masked softmax + gather into C = -prob   (~36us, memory-bound)
// ---------------------------------------------------------------------------
__global__ __launch_bounds__(256) void k_softmax_gather(
    const float* __restrict__ logits,
    const int*   __restrict__ tgt,
    const int*   __restrict__ mask,
    const int*   __restrict__ useBg,
    float*       __restrict__ out)
{
    __shared__ float sh[NC];
    __shared__ int   st[BT];
    __shared__ float red[8];

    const int row = blockIdx.x;
    const int tid = threadIdx.x;
    const int lane = tid & 31;
    const int warp = tid >> 5;

    const bool active = (useBg[0] != 0) || (mask[row] != 0);
    float* orow = out + (size_t)row * BT;

    if (!active) {
        const float4 z = make_float4(-0.0f, -0.0f, -0.0f, -0.0f);
        float4* o4 = (float4*)orow;
        #pragma unroll
        for (int j = tid; j < BT / 4; j += 256) o4[j] = z;
        return;
    }

    {
        const int4* tg4 = (const int4*)tgt;
        int4* st4 = (int4*)st;
        for (int j = tid; j < BT / 4; j += 256) st4[j] = tg4[j];
    }

    const float4* l4 = (const float4*)(logits + (size_t)row * NC);
    float4 v0 = l4[tid];
    float4 v1 = l4[tid + 256];

    float m = fmaxf(fmaxf(fmaxf(v0.x, v0.y), fmaxf(v0.z, v0.w)),
                    fmaxf(fmaxf(v1.x, v1.y), fmaxf(v1.z, v1.w)));
    #pragma unroll
    for (int o = 16; o; o >>= 1) m = fmaxf(m, __shfl_xor_sync(0xffffffffu, m, o));
    if (lane == 0) red[warp] = m;
    __syncthreads();
    if (tid == 0) {
        float t = red[0];
        #pragma unroll
        for (int w = 1; w < 8; w++) t = fmaxf(t, red[w]);
        red[0] = t;
    }
    __syncthreads();
    m = red[0];
    __syncthreads();

    float4 e0, e1;
    e0.x = expf(v0.x - m); e0.y = expf(v0.y - m);
    e0.z = expf(v0.z - m); e0.w = expf(v0.w - m);
    e1.x = expf(v1.x - m); e1.y = expf(v1.y - m);
    e1.z = expf(v1.z - m); e1.w = expf(v1.w - m);
    float s = (e0.x + e0.y) + (e0.z + e0.w) + (e1.x + e1.y) + (e1.z + e1.w);
    #pragma unroll
    for (int o = 16; o; o >>= 1) s += __shfl_xor_sync(0xffffffffu, s, o);
    if (lane == 0) red[warp] = s;
    __syncthreads();
    if (tid == 0) {
        float t = red[0];
        #pragma unroll
        for (int w = 1; w < 8; w++) t += red[w];
        red[0] = t;
    }
    __syncthreads();
    const float S = red[0];

    float4 p0, p1;
    p0.x = e0.x / S; p0.y = e0.y / S; p0.z = e0.z / S; p0.w = e0.w / S;
    p1.x = e1.x / S; p1.y = e1.y / S; p1.z = e1.z / S; p1.w = e1.w / S;
    ((float4*)sh)[tid]       = p0;
    ((float4*)sh)[tid + 256] = p1;
    __syncthreads();

    float4* o4 = (float4*)orow;
    const int4* st4 = (const int4*)st;
    #pragma unroll
    for (int j = tid; j < BT / 4; j += 256) {
        int4 id = st4[j];
        float4 o;
        o.x = -sh[id.x];
        o.y = -sh[id.y];
        o.z = -sh[id.z];
        o.w = -sh[id.w];
        o4[j] = o;
    }
}

// ---------------------------------------------------------------------------
// Kernel 2: Jonker-Volgenant (scipy-exact f64 arithmetic), one block/batch.
// Warp 0 solves; lane owns columns j = lane + 32k (k<8). Latency-oriented:
// row4col / u[row4col] are register-resident per lane, delivered through the
// argmin shuffle, so the pop loop has a single LDS (cost row) on its chain.
// ---------------------------------------------------------------------------
__global__ __launch_bounds__(256) void k_hungarian(
    const float* __restrict__ C,
    float* __restrict__ rows_out,
    float* __restrict__ cols_out)
{
    extern __shared__ float cost[];       // [NT * NQ] transposed block
    __shared__ double u[NT];
    __shared__ double dsh[NQ];            // exact d at popped (SC) columns
    __shared__ int path[NQ];
    __shared__ int row4col[NQ];
    __shared__ int col4row[NT];

    const int b = blockIdx.x;
    const int tid = threadIdx.x;

    // load + transpose [NQ x NT] diagonal block into cost[t*NQ + q]
    {
        const float4* src = (const float4*)(C + ((size_t)(b * NQ + tid)) * BT + b * NT);
        #pragma unroll
        for (int t4 = 0; t4 < NT / 4; t4++) {
            float4 vv = src[t4];
            int t = t4 * 4;
            cost[(t + 0) * NQ + tid] = vv.x;
            cost[(t + 1) * NQ + tid] = vv.y;
            cost[(t + 2) * NQ + tid] = vv.z;
            cost[(t + 3) * NQ + tid] = vv.w;
        }
    }
    if (tid < NT) { u[tid] = 0.0; col4row[tid] = -1; }
    row4col[tid] = -1;
    __syncthreads();

    if (tid >= 32) return;   // warp 0 only
    const int lane = tid;
    const unsigned FULL = 0xffffffffu;
    const unsigned long long KEYMAX = 0xFFFFFFFFFFFFFFFFULL;
    const unsigned long long KINF = dkey(CUDART_INF);

    double vreg[8];     // exact v (f64), lane's columns
    int    rjreg[8];    // row4col[j] for lane's columns (valid during search)
    double ureg[8];     // u[row4col[j]] for lane's columns
    #pragma unroll
    for (int k = 0; k < 8; k++) { vreg[k] = 0.0; rjreg[k] = -1; ureg[k] = 0.0; }

    for (int cur = 0; cur < NT; cur++) {
        unsigned long long dk[8];
        #pragma unroll
        for (int k = 0; k < 8; k++) dk[k] = KINF;
        unsigned sc = 0;        // SC bits for lane's 8 columns
        unsigned srbits = 0;    // SR bits for lane's 4 rows (row = lane + 32k)
        double minVal = 0.0;
        int i = cur;
        double ui = u[cur];
        int sink, bestj;

        for (;;) {
            // SR[i] = 1, register-resident (row owner lane)
            srbits |= (unsigned)((i & 31) == lane) << (i >> 5);

            const float* crow = cost + i * NQ;
            float c[8];
            #pragma unroll
            for (int k = 0; k < 8; k++) c[k] = crow[lane + 32 * k];

            // exact f64 relaxation, scipy order: ((minVal + cost) - u) - v
            #pragma unroll
            for (int k = 0; k < 8; k++) {
                if (!((sc >> k) & 1u)) {
                    double r = ((minVal + (double)c[k]) - ui) - vreg[k];
                    unsigned long long rk = dkey(r);
                    if (rk < dk[k]) {
                        dk[k] = rk;
                        path[lane + 32 * k] = i;
                    }
                }
            }

            // lane-local argmin tree with payload (ties -> lowest j == lowest k)
            unsigned long long K[8]; int J[8]; int R[8]; double Uc[8];
            #pragma unroll
            for (int k = 0; k < 8; k++) {
                K[k] = ((sc >> k) & 1u) ? KEYMAX : dk[k];
                J[k] = lane + 32 * k;
                R[k] = rjreg[k];
                Uc[k] = ureg[k];
            }
            #pragma unroll
            for (int s = 1; s < 8; s <<= 1) {
                #pragma unroll
                for (int k = 0; k < 8; k += 2 * s) {
                    if (K[k + s] < K[k]) {
                        K[k] = K[k + s]; J[k] = J[k + s];
                        R[k] = R[k + s]; Uc[k] = Uc[k + s];
                    }
                }
            }

            // warp argmin: REDUX on hi32, ballot fast-path with payload shuffles
            unsigned hi = (unsigned)(K[0] >> 32);
            unsigned lo = (unsigned)K[0];
            unsigned mhi = __reduce_min_sync(FULL, hi);
            unsigned bal = __ballot_sync(FULL, hi == mhi);
            unsigned mlo;
            int rj; double unext;
            if (__popc(bal) == 1) {
                const int src = __ffs(bal) - 1;
                mlo   = __shfl_sync(FULL, lo, src);
                bestj = __shfl_sync(FULL, J[0], src);
                rj    = __shfl_sync(FULL, R[0], src);
                unext = __shfl_sync(FULL, Uc[0], src);
            } else {
                unsigned lo2 = (hi == mhi) ? lo : 0xFFFFFFFFu;
                mlo = __reduce_min_sync(FULL, lo2);
                unsigned jc = (hi == mhi && lo == mlo) ? (unsigned)J[0] : 0xFFFFFFFFu;
                bestj = (int)__reduce_min_sync(FULL, jc);
                rj = row4col[bestj];
                unext = (rj >= 0) ? u[rj] : 0.0;
            }
            minVal = dunkey(((unsigned long long)mhi << 32) | mlo);
            if ((bestj & 31) == lane) {
                sc |= 1u << (bestj >> 5);
                dsh[bestj] = minVal;
            }
            if (rj < 0) { sink = bestj; break; }
            i = rj;
            ui = unext;
        }
        __syncwarp();

        // dual updates (scipy order; all f64); row-owner lanes update u
        #pragma unroll
        for (int k = 0; k < 4; k++) {
            if ((srbits >> k) & 1u) {
                const int r = lane + 32 * k;
                if (r == cur) {
                    u[r] = u[r] + minVal;
                } else {
                    const int j = col4row[r];
                    u[r] = u[r] + (minVal - dsh[j]);
                }
            }
        }
        #pragma unroll
        for (int k = 0; k < 8; k++) {
            if ((sc >> k) & 1u)
                vreg[k] = vreg[k] - (minVal - dunkey(dk[k]));
        }
        __syncwarp();

        // augment along shortest path (lane 0 serial)
        if (lane == 0) {
            int j = sink;
            while (true) {
                const int ii = path[j];
                row4col[j] = ii;
                const int jn = col4row[ii];
                col4row[ii] = j;
                j = jn;
                if (ii == cur) break;
            }
        }
        __syncwarp();

        // refresh register-resident row4col / u[row4col] for lane's columns
        #pragma unroll
        for (int k = 0; k < 8; k++) {
            const int j = lane + 32 * k;
            const int rj = row4col[j];
            rjreg[k] = rj;
            ureg[k] = (rj >= 0) ? u[rj] : 0.0;
        }
        __syncwarp();
    }

    // emit: rows = sorted assigned queries, cols = corresponding targets
    #pragma unroll
    for (int k = 0; k < 4; k++) {
        const int t = lane + 32 * k;
        const int q = col4row[t];
        int rank = 0;
        for (int t2 = 0; t2 < NT; t2++) rank += (col4row[t2] < q) ? 1 : 0;
        rows_out[b * NT + rank] = (float)q;
        cols_out[b * NT + rank] = (float)t;
    }
}

// ---------------------------------------------------------------------------
extern "C" void kernel_launch(void* const* d_in, const int* in_sizes, int n_in,
                              void* d_out, int out_size)
{
    const float* logits = (const float*)d_in[0];   // [32,256,2048] f32
    const int*   tgt    = (const int*)d_in[1];     // [32,128] i32
    const int*   mask   = (const int*)d_in[2];     // [32,256] i32
    const int*   useBg  = (const int*)d_in[3];     // [1] i32

    float* out  = (float*)d_out;
    float* rows = out + CSIZE;
    float* cols = rows + (size_t)BS * NT;

    k_softmax_gather<<<BS * NQ, 256>>>(logits, tgt, mask, useBg, out);

    cudaFuncSetAttribute(k_hungarian, cudaFuncAttributeMaxDynamicSharedMemorySize,
                         NT * NQ * (int)sizeof(float));
    k_hungarian<<<BS, 256, NT * NQ * sizeof(float)>>>(out, rows, cols);
}

// round 7
// speedup vs baseline: 1.0283x; 1.0283x over previous
#include <cuda_runtime.h>
#include <math_constants.h>

#define BS 32
#define NQ 256
#define NT 128
#define NC 2048
#define BT (BS * NT)                  // 4096
#define CSIZE ((size_t)BS * NQ * BT)  // 33554432

// Sortable-integer mapping for IEEE f64 (no NaN / -0.0 appears here):
// unsigned order of keys == numeric order of doubles.
static __device__ __forceinline__ unsigned long long dkey(double x) {
    unsigned long long b = (unsigned long long)__double_as_longlong(x);
    return (b & 0x8000000000000000ULL) ? ~b : (b | 0x8000000000000000ULL);
}
static __device__ __forceinline__ double dunkey(unsigned long long k) {
    unsigned long long b = (k & 0x8000000000000000ULL) ? (k ^ 0x8000000000000000ULL) : ~k;
    return __longlong_as_double((long long)b);
}

// ---------------------------------------------------------------------------
// Kernel 1: masked softmax + gather into C = -prob   (~36us, memory-bound)
// ---------------------------------------------------------------------------
__global__ __launch_bounds__(256) void k_softmax_gather(
    const float* __restrict__ logits,
    const int*   __restrict__ tgt,
    const int*   __restrict__ mask,
    const int*   __restrict__ useBg,
    float*       __restrict__ out)
{
    __shared__ float sh[NC];
    __shared__ int   st[BT];
    __shared__ float red[8];

    const int row = blockIdx.x;
    const int tid = threadIdx.x;
    const int lane = tid & 31;
    const int warp = tid >> 5;

    const bool active = (useBg[0] != 0) || (mask[row] != 0);
    float* orow = out + (size_t)row * BT;

    if (!active) {
        const float4 z = make_float4(-0.0f, -0.0f, -0.0f, -0.0f);
        float4* o4 = (float4*)orow;
        #pragma unroll
        for (int j = tid; j < BT / 4; j += 256) o4[j] = z;
        return;
    }

    {
        const int4* tg4 = (const int4*)tgt;
        int4* st4 = (int4*)st;
        for (int j = tid; j < BT / 4; j += 256) st4[j] = tg4[j];
    }

    const float4* l4 = (const float4*)(logits + (size_t)row * NC);
    float4 v0 = l4[tid];
    float4 v1 = l4[tid + 256];

    float m = fmaxf(fmaxf(fmaxf(v0.x, v0.y), fmaxf(v0.z, v0.w)),
                    fmaxf(fmaxf(v1.x, v1.y), fmaxf(v1.z, v1.w)));
    #pragma unroll
    for (int o = 16; o; o >>= 1) m = fmaxf(m, __shfl_xor_sync(0xffffffffu, m, o));
    if (lane == 0) red[warp] = m;
    __syncthreads();
    if (tid == 0) {
        float t = red[0];
        #pragma unroll
        for (int w = 1; w < 8; w++) t = fmaxf(t, red[w]);
        red[0] = t;
    }
    __syncthreads();
    m = red[0];
    __syncthreads();

    float4 e0, e1;
    e0.x = expf(v0.x - m); e0.y = expf(v0.y - m);
    e0.z = expf(v0.z - m); e0.w = expf(v0.w - m);
    e1.x = expf(v1.x - m); e1.y = expf(v1.y - m);
    e1.z = expf(v1.z - m); e1.w = expf(v1.w - m);
    float s = (e0.x + e0.y) + (e0.z + e0.w) + (e1.x + e1.y) + (e1.z + e1.w);
    #pragma unroll
    for (int o = 16; o; o >>= 1) s += __shfl_xor_sync(0xffffffffu, s, o);
    if (lane == 0) red[warp] = s;
    __syncthreads();
    if (tid == 0) {
        float t = red[0];
        #pragma unroll
        for (int w = 1; w < 8; w++) t += red[w];
        red[0] = t;
    }
    __syncthreads();
    const float S = red[0];

    float4 p0, p1;
    p0.x = e0.x / S; p0.y = e0.y / S; p0.z = e0.z / S; p0.w = e0.w / S;
    p1.x = e1.x / S; p1.y = e1.y / S; p1.z = e1.z / S; p1.w = e1.w / S;
    ((float4*)sh)[tid]       = p0;
    ((float4*)sh)[tid + 256] = p1;
    __syncthreads();

    float4* o4 = (float4*)orow;
    const int4* st4 = (const int4*)st;
    #pragma unroll
    for (int j = tid; j < BT / 4; j += 256) {
        int4 id = st4[j];
        float4 o;
        o.x = -sh[id.x];
        o.y = -sh[id.y];
        o.z = -sh[id.z];
        o.w = -sh[id.w];
        o4[j] = o;
    }
}

// ---------------------------------------------------------------------------
// Kernel 2: Jonker-Volgenant (scipy-exact f64 arithmetic), one block/batch.
// Warp 0 solves; lane owns columns j = lane + 32k (k<8).
// Tie-drain: after a pop at key 'minkey', if no non-SC key < minkey and some
// non-SC key == minkey, the sequential next pop is the lowest such j (strict-<
// relaxation cannot alter tied entries, and minVal/path/duals are unchanged),
// found via integer compares + ballot + REDUX instead of the full argmin.
// Any violation (ulp-negative reduced cost) falls back to the full argmin,
// which is exactly the sequential semantics. Bit-identical to scipy.
// ---------------------------------------------------------------------------
__global__ __launch_bounds__(256) void k_hungarian(
    const float* __restrict__ C,
    float* __restrict__ rows_out,
    float* __restrict__ cols_out)
{
    extern __shared__ float cost[];       // [NT * NQ] transposed block
    __shared__ double u[NT];
    __shared__ double dsh[NQ];            // exact d at popped (SC) columns
    __shared__ int path[NQ];
    __shared__ int row4col[NQ];
    __shared__ int col4row[NT];

    const int b = blockIdx.x;
    const int tid = threadIdx.x;

    // load + transpose [NQ x NT] diagonal block into cost[t*NQ + q]
    {
        const float4* src = (const float4*)(C + ((size_t)(b * NQ + tid)) * BT + b * NT);
        #pragma unroll
        for (int t4 = 0; t4 < NT / 4; t4++) {
            float4 vv = src[t4];
            int t = t4 * 4;
            cost[(t + 0) * NQ + tid] = vv.x;
            cost[(t + 1) * NQ + tid] = vv.y;
            cost[(t + 2) * NQ + tid] = vv.z;
            cost[(t + 3) * NQ + tid] = vv.w;
        }
    }
    if (tid < NT) { u[tid] = 0.0; col4row[tid] = -1; }
    row4col[tid] = -1;
    __syncthreads();

    if (tid >= 32) return;   // warp 0 only
    const int lane = tid;
    const unsigned FULL = 0xffffffffu;
    const unsigned long long KEYMAX = 0xFFFFFFFFFFFFFFFFULL;
    const unsigned long long KINF = dkey(CUDART_INF);

    double vreg[8];     // exact v (f64), lane's columns
    #pragma unroll
    for (int k = 0; k < 8; k++) vreg[k] = 0.0;

    for (int cur = 0; cur < NT; cur++) {
        unsigned long long dk[8];
        #pragma unroll
        for (int k = 0; k < 8; k++) dk[k] = KINF;
        unsigned sc = 0;        // SC bits for lane's 8 columns
        unsigned srbits = 0;    // SR bits for lane's 4 rows (row = lane + 32k)
        double minVal = 0.0;
        unsigned long long minkey = 0;
        bool have_key = false;
        int i = cur;
        double ui = u[cur];
        int sink;

        for (;;) {
            // SR[i] = 1 (register-resident, row-owner lane)
            srbits |= (unsigned)((i & 31) == lane) << (i >> 5);

            // relax row i: scipy order ((minVal + cost) - u) - v, all f64
            const float* crow = cost + i * NQ;
            float c[8];
            #pragma unroll
            for (int k = 0; k < 8; k++) c[k] = crow[lane + 32 * k];
            #pragma unroll
            for (int k = 0; k < 8; k++) {
                if (!((sc >> k) & 1u)) {
                    double r = ((minVal + (double)c[k]) - ui) - vreg[k];
                    unsigned long long rk = dkey(r);
                    if (rk < dk[k]) {
                        dk[k] = rk;
                        path[lane + 32 * k] = i;
                    }
                }
            }

            int bestj;
            bool need_full = true;

            if (have_key) {
                // cheap tie-drain check vs current minkey
                unsigned eqm = 0, ltm = 0;
                #pragma unroll
                for (int k = 0; k < 8; k++) {
                    if (!((sc >> k) & 1u)) {
                        eqm |= (unsigned)(dk[k] == minkey) << k;
                        ltm |= (unsigned)(dk[k] <  minkey) << k;
                    }
                }
                unsigned anylt = __ballot_sync(FULL, ltm != 0);
                unsigned anyeq = __ballot_sync(FULL, eqm != 0);
                if (anylt == 0 && anyeq != 0) {
                    // next sequential pop = lowest j with key == minkey
                    unsigned cand = eqm ? ((unsigned)((__ffs(eqm) - 1) << 5) | (unsigned)lane)
                                        : 0xFFFFFFFFu;
                    bestj = (int)__reduce_min_sync(FULL, cand);
                    need_full = false;
                }
            }

            if (need_full) {
                // lane-local argmin (ties -> lowest j == lowest k)
                unsigned long long K[8]; int J[8];
                #pragma unroll
                for (int k = 0; k < 8; k++) {
                    K[k] = ((sc >> k) & 1u) ? KEYMAX : dk[k];
                    J[k] = lane + 32 * k;
                }
                #pragma unroll
                for (int s = 1; s < 8; s <<= 1) {
                    #pragma unroll
                    for (int k = 0; k < 8; k += 2 * s) {
                        if (K[k + s] < K[k]) { K[k] = K[k + s]; J[k] = J[k + s]; }
                    }
                }
                // warp argmin: REDUX on hi32, ballot fast-path
                unsigned hi = (unsigned)(K[0] >> 32);
                unsigned lo = (unsigned)K[0];
                unsigned mhi = __reduce_min_sync(FULL, hi);
                unsigned bal = __ballot_sync(FULL, hi == mhi);
                unsigned mlo;
                if (__popc(bal) == 1) {
                    const int src = __ffs(bal) - 1;
                    mlo   = __shfl_sync(FULL, lo, src);
                    bestj = __shfl_sync(FULL, J[0], src);
                } else {
                    unsigned lo2 = (hi == mhi) ? lo : 0xFFFFFFFFu;
                    mlo = __reduce_min_sync(FULL, lo2);
                    unsigned jc = (hi == mhi && lo == mlo) ? (unsigned)J[0] : 0xFFFFFFFFu;
                    bestj = (int)__reduce_min_sync(FULL, jc);
                }
                minkey = ((unsigned long long)mhi << 32) | mlo;
                minVal = dunkey(minkey);
                have_key = true;
            }

            // pop bestj
            if ((bestj & 31) == lane) {
                sc |= 1u << (bestj >> 5);
                dsh[bestj] = minVal;
            }
            const int rj = row4col[bestj];
            if (rj < 0) { sink = bestj; break; }
            i = rj;
            ui = u[rj];
        }
        __syncwarp();

        // dual updates (scipy order; all f64); row-owner lanes update u
        #pragma unroll
        for (int k = 0; k < 4; k++) {
            if ((srbits >> k) & 1u) {
                const int r = lane + 32 * k;
                if (r == cur) {
                    u[r] = u[r] + minVal;
                } else {
                    const int j = col4row[r];
                    u[r] = u[r] + (minVal - dsh[j]);
                }
            }
        }
        #pragma unroll
        for (int k = 0; k < 8; k++) {
            if ((sc >> k) & 1u)
                vreg[k] = vreg[k] - (minVal - dunkey(dk[k]));
        }
        __syncwarp();

        // augment along shortest path (lane 0 serial)
        if (lane == 0) {
            int j = sink;
            while (true) {
                const int ii = path[j];
                row4col[j] = ii;
                const int jn = col4row[ii];
                col4row[ii] = j;
                j = jn;
                if (ii == cur) break;
            }
        }
        __syncwarp();
    }

    // emit: rows = sorted assigned queries, cols = corresponding targets
    #pragma unroll
    for (int k = 0; k < 4; k++) {
        const int t = lane + 32 * k;
        const int q = col4row[t];
        int rank = 0;
        for (int t2 = 0; t2 < NT; t2++) rank += (col4row[t2] < q) ? 1 : 0;
        rows_out[b * NT + rank] = (float)q;
        cols_out[b * NT + rank] = (float)t;
    }
}

// ---------------------------------------------------------------------------
extern "C" void kernel_launch(void* const* d_in, const int* in_sizes, int n_in,
                              void* d_out, int out_size)
{
    const float* logits = (const float*)d_in[0];   // [32,256,2048] f32
    const int*   tgt    = (const int*)d_in[1];     // [32,128] i32
    const int*   mask   = (const int*)d_in[2];     // [32,256] i32
    const int*   useBg  = (const int*)d_in[3];     // [1] i32

    float* out  = (float*)d_out;
    float* rows = out + CSIZE;
    float* cols = rows + (size_t)BS * NT;

    k_softmax_gather<<<BS * NQ, 256>>>(logits, tgt, mask, useBg, out);

    cudaFuncSetAttribute(k_hungarian, cudaFuncAttributeMaxDynamicSharedMemorySize,
                         NT * NQ * (int)sizeof(float));
    k_hungarian<<<BS, 256, NT * NQ * sizeof(float)>>>(out, rows, cols);
}

// round 8
// speedup vs baseline: 1.1162x; 1.0855x over previous
#include <cuda_runtime.h>
#include <math_constants.h>

#define BS 32
#define NQ 256
#define NT 128
#define NC 2048
#define BT (BS * NT)                  // 4096
#define CSIZE ((size_t)BS * NQ * BT)  // 33554432
#define GRIDPAD 148                   // >=148 avoids low-grid issue throttle

// Sortable-integer mapping for IEEE f64 (no NaN / -0.0 appears here):
// unsigned order of keys == numeric order of doubles.
static __device__ __forceinline__ unsigned long long dkey(double x) {
    unsigned long long b = (unsigned long long)__double_as_longlong(x);
    return (b & 0x8000000000000000ULL) ? ~b : (b | 0x8000000000000000ULL);
}
static __device__ __forceinline__ double dunkey(unsigned long long k) {
    unsigned long long b = (k & 0x8000000000000000ULL) ? (k ^ 0x8000000000000000ULL) : ~k;
    return __longlong_as_double((long long)b);
}

// ---------------------------------------------------------------------------
// Kernel 1: masked softmax + gather into C = -prob   (~36us, memory-bound)
// ---------------------------------------------------------------------------
__global__ __launch_bounds__(256) void k_softmax_gather(
    const float* __restrict__ logits,
    const int*   __restrict__ tgt,
    const int*   __restrict__ mask,
    const int*   __restrict__ useBg,
    float*       __restrict__ out)
{
    __shared__ float sh[NC];
    __shared__ int   st[BT];
    __shared__ float red[8];

    const int row = blockIdx.x;
    const int tid = threadIdx.x;
    const int lane = tid & 31;
    const int warp = tid >> 5;

    const bool active = (useBg[0] != 0) || (mask[row] != 0);
    float* orow = out + (size_t)row * BT;

    if (!active) {
        const float4 z = make_float4(-0.0f, -0.0f, -0.0f, -0.0f);
        float4* o4 = (float4*)orow;
        #pragma unroll
        for (int j = tid; j < BT / 4; j += 256) o4[j] = z;
        return;
    }

    {
        const int4* tg4 = (const int4*)tgt;
        int4* st4 = (int4*)st;
        for (int j = tid; j < BT / 4; j += 256) st4[j] = tg4[j];
    }

    const float4* l4 = (const float4*)(logits + (size_t)row * NC);
    float4 v0 = l4[tid];
    float4 v1 = l4[tid + 256];

    float m = fmaxf(fmaxf(fmaxf(v0.x, v0.y), fmaxf(v0.z, v0.w)),
                    fmaxf(fmaxf(v1.x, v1.y), fmaxf(v1.z, v1.w)));
    #pragma unroll
    for (int o = 16; o; o >>= 1) m = fmaxf(m, __shfl_xor_sync(0xffffffffu, m, o));
    if (lane == 0) red[warp] = m;
    __syncthreads();
    if (tid == 0) {
        float t = red[0];
        #pragma unroll
        for (int w = 1; w < 8; w++) t = fmaxf(t, red[w]);
        red[0] = t;
    }
    __syncthreads();
    m = red[0];
    __syncthreads();

    float4 e0, e1;
    e0.x = expf(v0.x - m); e0.y = expf(v0.y - m);
    e0.z = expf(v0.z - m); e0.w = expf(v0.w - m);
    e1.x = expf(v1.x - m); e1.y = expf(v1.y - m);
    e1.z = expf(v1.z - m); e1.w = expf(v1.w - m);
    float s = (e0.x + e0.y) + (e0.z + e0.w) + (e1.x + e1.y) + (e1.z + e1.w);
    #pragma unroll
    for (int o = 16; o; o >>= 1) s += __shfl_xor_sync(0xffffffffu, s, o);
    if (lane == 0) red[warp] = s;
    __syncthreads();
    if (tid == 0) {
        float t = red[0];
        #pragma unroll
        for (int w = 1; w < 8; w++) t += red[w];
        red[0] = t;
    }
    __syncthreads();
    const float S = red[0];

    float4 p0, p1;
    p0.x = e0.x / S; p0.y = e0.y / S; p0.z = e0.z / S; p0.w = e0.w / S;
    p1.x = e1.x / S; p1.y = e1.y / S; p1.z = e1.z / S; p1.w = e1.w / S;
    ((float4*)sh)[tid]       = p0;
    ((float4*)sh)[tid + 256] = p1;
    __syncthreads();

    float4* o4 = (float4*)orow;
    const int4* st4 = (const int4*)st;
    #pragma unroll
    for (int j = tid; j < BT / 4; j += 256) {
        int4 id = st4[j];
        float4 o;
        o.x = -sh[id.x];
        o.y = -sh[id.y];
        o.z = -sh[id.z];
        o.w = -sh[id.w];
        o4[j] = o;
    }
}

// ---------------------------------------------------------------------------
// Kernel 2: Jonker-Volgenant (scipy-exact f64 arithmetic), one block/batch.
// Warp 0 solves; lane owns columns j = lane + 32k (k<8).
// Straight-line pop loop: no divergent fast paths. Relaxation DADDs run
// unconditionally; updates are predicated. Exactly one data-dependent
// branch (sink test) per pop.
// ---------------------------------------------------------------------------
__global__ __launch_bounds__(256) void k_hungarian(
    const float* __restrict__ C,
    float* __restrict__ rows_out,
    float* __restrict__ cols_out)
{
    extern __shared__ float cost[];       // [NT * NQ] transposed block
    __shared__ double u[NT];
    __shared__ double dsh[NQ];            // exact d at popped (SC) columns
    __shared__ int path[NQ];
    __shared__ int row4col[NQ];
    __shared__ int col4row[NT];

    const int b = blockIdx.x;
    if (b >= BS) return;                  // grid padded to dodge low-grid throttle
    const int tid = threadIdx.x;

    // load + transpose [NQ x NT] diagonal block into cost[t*NQ + q]
    {
        const float4* src = (const float4*)(C + ((size_t)(b * NQ + tid)) * BT + b * NT);
        #pragma unroll
        for (int t4 = 0; t4 < NT / 4; t4++) {
            float4 vv = src[t4];
            int t = t4 * 4;
            cost[(t + 0) * NQ + tid] = vv.x;
            cost[(t + 1) * NQ + tid] = vv.y;
            cost[(t + 2) * NQ + tid] = vv.z;
            cost[(t + 3) * NQ + tid] = vv.w;
        }
    }
    if (tid < NT) { u[tid] = 0.0; col4row[tid] = -1; }
    row4col[tid] = -1;
    __syncthreads();

    if (tid >= 32) return;   // warp 0 only
    const int lane = tid;
    const unsigned FULL = 0xffffffffu;
    const unsigned long long KEYMAX = 0xFFFFFFFFFFFFFFFFULL;
    const unsigned long long KINF = dkey(CUDART_INF);

    double vreg[8];
    #pragma unroll
    for (int k = 0; k < 8; k++) vreg[k] = 0.0;

    for (int cur = 0; cur < NT; cur++) {
        unsigned long long dk[8];
        #pragma unroll
        for (int k = 0; k < 8; k++) dk[k] = KINF;
        unsigned sc = 0;        // SC bits for lane's 8 columns
        unsigned srbits = 0;    // SR bits for lane's 4 rows (row = lane + 32k)
        double minVal = 0.0;
        int i = cur;
        double ui = u[cur];
        int sink;

        #pragma unroll 1
        for (;;) {
            // SR[i] = 1 (register-resident; branchless)
            srbits |= (unsigned)((i & 31) == lane) << (i >> 5);

            // relax row i: scipy order ((minVal + cost) - u) - v, all f64.
            // DADDs unconditional; update predicated on (!SC && rk < dk).
            const float* crow = cost + i * NQ;
            float c[8];
            #pragma unroll
            for (int k = 0; k < 8; k++) c[k] = crow[lane + 32 * k];
            #pragma unroll
            for (int k = 0; k < 8; k++) {
                double r = ((minVal + (double)c[k]) - ui) - vreg[k];
                unsigned long long rk = dkey(r);
                bool upd = (rk < dk[k]) & !((sc >> k) & 1u);
                if (upd) {
                    dk[k] = rk;
                    path[lane + 32 * k] = i;
                }
            }

            // lane-local argmin (ties -> lowest j == lowest k); SC masked
            unsigned long long K[8]; int J[8];
            #pragma unroll
            for (int k = 0; k < 8; k++) {
                K[k] = ((sc >> k) & 1u) ? KEYMAX : dk[k];
                J[k] = lane + 32 * k;
            }
            #pragma unroll
            for (int s = 1; s < 8; s <<= 1) {
                #pragma unroll
                for (int k = 0; k < 8; k += 2 * s) {
                    if (K[k + s] < K[k]) { K[k] = K[k + s]; J[k] = J[k + s]; }
                }
            }

            // warp argmin: straight-line 3x REDUX (no divergent fast path)
            unsigned hi = (unsigned)(K[0] >> 32);
            unsigned lo = (unsigned)K[0];
            unsigned mhi = __reduce_min_sync(FULL, hi);
            unsigned lo2 = (hi == mhi) ? lo : 0xFFFFFFFFu;
            unsigned mlo = __reduce_min_sync(FULL, lo2);
            unsigned jc  = (hi == mhi && lo == mlo) ? (unsigned)J[0] : 0xFFFFFFFFu;
            const int bestj = (int)__reduce_min_sync(FULL, jc);

            minVal = dunkey(((unsigned long long)mhi << 32) | mlo);

            // pop bookkeeping, branchless / predicated
            const bool owner = ((bestj & 31) == lane);
            sc |= (unsigned)owner << (bestj >> 5);
            if (owner) dsh[bestj] = minVal;     // single predicated STS

            const int rj = row4col[bestj];
            if (rj < 0) { sink = bestj; break; }
            i = rj;
            ui = u[rj];
        }
        __syncwarp();

        // dual updates (scipy order; all f64); row-owner lanes update u
        #pragma unroll
        for (int k = 0; k < 4; k++) {
            if ((srbits >> k) & 1u) {
                const int r = lane + 32 * k;
                if (r == cur) {
                    u[r] = u[r] + minVal;
                } else {
                    const int j = col4row[r];
                    u[r] = u[r] + (minVal - dsh[j]);
                }
            }
        }
        #pragma unroll
        for (int k = 0; k < 8; k++) {
            if ((sc >> k) & 1u)
                vreg[k] = vreg[k] - (minVal - dunkey(dk[k]));
        }
        __syncwarp();

        // augment along shortest path (lane 0 serial)
        if (lane == 0) {
            int j = sink;
            while (true) {
                const int ii = path[j];
                row4col[j] = ii;
                const int jn = col4row[ii];
                col4row[ii] = j;
                j = jn;
                if (ii == cur) break;
            }
        }
        __syncwarp();
    }

    // emit: rows = sorted assigned queries, cols = corresponding targets
    #pragma unroll
    for (int k = 0; k < 4; k++) {
        const int t = lane + 32 * k;
        const int q = col4row[t];
        int rank = 0;
        for (int t2 = 0; t2 < NT; t2++) rank += (col4row[t2] < q) ? 1 : 0;
        rows_out[b * NT + rank] = (float)q;
        cols_out[b * NT + rank] = (float)t;
    }
}

// ---------------------------------------------------------------------------
extern "C" void kernel_launch(void* const* d_in, const int* in_sizes, int n_in,
                              void* d_out, int out_size)
{
    const float* logits = (const float*)d_in[0];   // [32,256,2048] f32
    const int*   tgt    = (const int*)d_in[1];     // [32,128] i32
    const int*   mask   = (const int*)d_in[2];     // [32,256] i32
    const int*   useBg  = (const int*)d_in[3];     // [1] i32

    float* out  = (float*)d_out;
    float* rows = out + CSIZE;
    float* cols = rows + (size_t)BS * NT;

    k_softmax_gather<<<BS * NQ, 256>>>(logits, tgt, mask, useBg, out);

    cudaFuncSetAttribute(k_hungarian, cudaFuncAttributeMaxDynamicSharedMemorySize,
                         NT * NQ * (int)sizeof(float));
    k_hungarian<<<GRIDPAD, 256, NT * NQ * sizeof(float)>>>(out, rows, cols);
}